// round 2
// baseline (speedup 1.0000x reference)
#include <cuda_runtime.h>

#define HALFW 6
#define MAXC  63
#define NK    21
#define NB    64
#define NC    256
#define NH    64
#define NW    64
#define HW    (NH * NW)
#define XBLK  4          // grid.x: blocks along hw (each covers 16 rows)

// Per-block partial box sums: [t][b][xblk][k]  (raw channel-sums, no /256, no /cnt)
__device__ float g_part[2][NB][XBLK][NK];

// ---------------------------------------------------------------------------
// Kernel 1 (fused): channel reduce + per-tile box partial sums.
// block = 512 threads: 256 hw4 positions x 2 channel-halves.
// grid  = (XBLK=4, B=64, 2).  Each block owns a 16-row x 64-col fm tile.
// ---------------------------------------------------------------------------
__global__ void __launch_bounds__(512) fused_main_kernel(
    const float* __restrict__ f1, const float* __restrict__ f2,
    const int* __restrict__ pre1, const int* __restrict__ pre2)
{
    const int t     = blockIdx.z;
    const int b     = blockIdx.y;
    const int tid   = threadIdx.x;
    const int chalf = tid >> 8;          // 0/1: which 128-channel half
    const int i     = tid & 255;         // hw4 index within block (0..255)
    const int hw4   = blockIdx.x * 256 + i;

    const float4* __restrict__ f4 =
        reinterpret_cast<const float4*>(t == 0 ? f1 : f2);
    const float4* __restrict__ p =
        f4 + (size_t)b * NC * (HW / 4) + (size_t)chalf * 128 * (HW / 4) + hw4;

    float4 acc = make_float4(0.f, 0.f, 0.f, 0.f);
#pragma unroll 8
    for (int c = 0; c < 128; ++c) {
        float4 v = __ldcs(&p[(size_t)c * (HW / 4)]);
        acc.x += v.x; acc.y += v.y; acc.z += v.z; acc.w += v.w;
    }

    __shared__ float4 s_half[2][256];     // per-half partials
    __shared__ float  s_fm[16][NW];       // combined fm tile (x 256, raw ch-sum)
    __shared__ int    s_pre[2 * NK];      // this batch's 21 (x,y) pairs

    s_half[chalf][i] = acc;
    if (tid < 2 * NK)
        s_pre[tid] = (t == 0 ? pre1 : pre2)[b * 2 * NK + tid];
    __syncthreads();

    if (chalf == 0) {
        float4 a = s_half[0][i];
        float4 c2 = s_half[1][i];
        const int lr = i >> 4;            // local row (0..15)
        const int lw = (i & 15) * 4;      // col base
        s_fm[lr][lw + 0] = a.x + c2.x;
        s_fm[lr][lw + 1] = a.y + c2.y;
        s_fm[lr][lw + 2] = a.z + c2.z;
        s_fm[lr][lw + 3] = a.w + c2.w;
    }
    __syncthreads();

    // Box partials: warp w handles keypoints w, w+16. Deterministic shuffles.
    const int warp = tid >> 5;
    const int lane = tid & 31;
    const int r0   = blockIdx.x * 16;     // global row base of this tile

    for (int k = warp; k < NK; k += 16) {
        const int x = s_pre[2 * k + 0];
        const int y = s_pre[2 * k + 1];
        // x masks rows (H), y masks cols (W); exclusive upper bounds.
        const int left  = max(x - HALFW, 0);
        const int right = min(x + HALFW, MAXC);
        const int down  = max(y - HALFW, 0);
        const int up    = min(y + HALFW, MAXC);

        const int rl = max(left, r0);
        const int rr = min(right, r0 + 16);
        const int nw = up - down;                 // 6..12
        const int ncell = (rr - rl) * nw;         // may be <= 0

        float s = 0.f;
        for (int idx = lane; idx < ncell; idx += 32) {
            const int lr = (rl - r0) + idx / nw;
            const int w  = down + idx % nw;
            s += s_fm[lr][w];
        }
#pragma unroll
        for (int off = 16; off > 0; off >>= 1)
            s += __shfl_down_sync(0xffffffffu, s, off);
        if (lane == 0)
            g_part[t][b][blockIdx.x][k] = s;      // every slot written each call
    }
}

// ---------------------------------------------------------------------------
// Kernel 2: finish. 1 block, 1024 threads = 16 groups x 64 batch-lanes.
// Fully deterministic tree reductions; no atomics.
// ---------------------------------------------------------------------------
__global__ void __launch_bounds__(1024) finish_kernel(
    const int* __restrict__ pre1, const int* __restrict__ pre2,
    float* __restrict__ out)
{
    __shared__ float red[16][NB];
    __shared__ float s_fea[2 * NK];

    const int tid = threadIdx.x;
    const int ty  = tid >> 6;     // 0..15 group
    const int tx  = tid & 63;     // batch index

#pragma unroll
    for (int gi = 0; gi < 3; ++gi) {
        const int g = ty + 16 * gi;           // 0..47, valid if < 42
        float v = 0.f;
        if (g < 2 * NK) {
            const int t = g / NK;
            const int k = g % NK;
            const int* __restrict__ pre = (t == 0) ? pre1 : pre2;
            const int x = pre[(tx * NK + k) * 2 + 0];
            const int y = pre[(tx * NK + k) * 2 + 1];
            const int cnt = (min(x + HALFW, MAXC) - max(x - HALFW, 0)) *
                            (min(y + HALFW, MAXC) - max(y - HALFW, 0));
            float s = 0.f;
#pragma unroll
            for (int xb = 0; xb < XBLK; ++xb)
                s += g_part[t][tx][xb][k];
            v = s / ((float)cnt * (float)NC);   // per-box mean
        }
        red[ty][tx] = v;
        __syncthreads();
#pragma unroll
        for (int off = 32; off > 0; off >>= 1) {
            if (tx < off) red[ty][tx] += red[ty][tx + off];
            __syncthreads();
        }
        if (tx == 0 && g < 2 * NK)
            s_fea[g] = red[ty][0] * (1.0f / (float)NB);
        __syncthreads();
    }

    if (tid == 0) {
        float acc = 0.f;
#pragma unroll
        for (int k = 0; k < NK; ++k) {
            const float d = s_fea[k] - 0.999f * s_fea[NK + k];
            acc += d * d;
        }
        out[0] = acc * (1.0f / (float)NK);
    }
}

extern "C" void kernel_launch(void* const* d_in, const int* in_sizes, int n_in,
                              void* d_out, int out_size)
{
    const float* f1   = (const float*)d_in[0];
    const float* f2   = (const float*)d_in[1];
    const int*   pre1 = (const int*)d_in[2];
    const int*   pre2 = (const int*)d_in[3];

    fused_main_kernel<<<dim3(XBLK, NB, 2), 512>>>(f1, f2, pre1, pre2);
    finish_kernel<<<1, 1024>>>(pre1, pre2, (float*)d_out);
}

// round 3
// speedup vs baseline: 1.1440x; 1.1440x over previous
#include <cuda_runtime.h>

#define HALFW 6
#define MAXC  63
#define NK    21
#define NB    64
#define NC    256
#define NH    64
#define NW    64
#define HW    (NH * NW)

// Scratch (allocation-free rule: __device__ globals)
__device__ float g_fm[2][NB][NH][NW];   // channel means, 2 MiB
__device__ float g_fea[2][NK];          // per-keypoint batch-mean box means
__device__ int   g_count = 0;           // completion counter (self-resetting)

// ---------------------------------------------------------------------------
// Kernel 1: fm[t][b][h][w] = (1/256) * sum_c f[b][c][h][w]
// PROVEN at 80.4us / 85% DRAM — unchanged from round 1.
// grid = (HW/(256*4), B, 2), block = 256
// ---------------------------------------------------------------------------
__global__ void __launch_bounds__(256) chan_mean_kernel(
    const float* __restrict__ f1, const float* __restrict__ f2)
{
    const int t   = blockIdx.z;
    const int b   = blockIdx.y;
    const int hw4 = blockIdx.x * blockDim.x + threadIdx.x;   // 0..1023

    const float4* __restrict__ f4 =
        reinterpret_cast<const float4*>(t == 0 ? f1 : f2);
    const float4* __restrict__ p = f4 + (size_t)b * NC * (HW / 4) + hw4;

    float4 acc = make_float4(0.f, 0.f, 0.f, 0.f);
#pragma unroll 8
    for (int c = 0; c < NC; ++c) {
        float4 v = p[(size_t)c * (HW / 4)];
        acc.x += v.x; acc.y += v.y; acc.z += v.z; acc.w += v.w;
    }
    const float s = 1.0f / (float)NC;
    float4 o = make_float4(acc.x * s, acc.y * s, acc.z * s, acc.w * s);
    reinterpret_cast<float4*>(&g_fm[t][b][0][0])[hw4] = o;
}

// ---------------------------------------------------------------------------
// Kernel 2 (fused): per-(tensor,keypoint) batch-mean box mean, then the
// last block to finish computes the MSE loss. One launch instead of two.
// grid = 42 blocks, block = 512 threads (64 batches x 8 threads per box).
// ---------------------------------------------------------------------------
__global__ void __launch_bounds__(512) box_loss_kernel(
    const int* __restrict__ pre1, const int* __restrict__ pre2,
    float* __restrict__ out)
{
    const int t   = blockIdx.x / NK;
    const int k   = blockIdx.x % NK;
    const int tid = threadIdx.x;
    const int b   = tid >> 3;
    const int j   = tid & 7;

    const int* __restrict__ pre = (t == 0) ? pre1 : pre2;
    const int x = pre[(b * NK + k) * 2 + 0];
    const int y = pre[(b * NK + k) * 2 + 1];

    // x masks rows (H), y masks cols (W); exclusive upper bounds.
    const int left  = max(x - HALFW, 0);
    const int right = min(x + HALFW, MAXC);
    const int down  = max(y - HALFW, 0);
    const int up    = min(y + HALFW, MAXC);

    const int nh = right - left;
    const int nw = up - down;
    const int ncell = nh * nw;                // cnt, always >= 36

    float s = 0.f;
    for (int i = j; i < ncell; i += 8) {
        const int h = left + i / nw;
        const int w = down + i % nw;
        s += g_fm[t][b][h][w];
    }
    s *= 1.0f / (float)ncell;                 // per-box mean

    __shared__ float red[512];
    __shared__ int   s_last;
    red[tid] = s;
    __syncthreads();
#pragma unroll
    for (int off = 256; off > 0; off >>= 1) {
        if (tid < off) red[tid] += red[tid + off];
        __syncthreads();
    }
    if (tid == 0) {
        g_fea[t][k] = red[0] * (1.0f / (float)NB);
        __threadfence();
        const int prev = atomicAdd(&g_count, 1);
        s_last = (prev == 2 * NK - 1) ? 1 : 0;
    }
    __syncthreads();

    // Last block computes the final loss (g_fea fully written; each slot
    // written exactly once per call -> deterministic numerics).
    if (s_last) {
        if (tid == 0) {
            __threadfence();
            float acc = 0.f;
#pragma unroll
            for (int kk = 0; kk < NK; ++kk) {
                const float d = g_fea[0][kk] - 0.999f * g_fea[1][kk];
                acc += d * d;
            }
            out[0] = acc * (1.0f / (float)NK);
            g_count = 0;                      // reset for next replay
        }
    }
}

extern "C" void kernel_launch(void* const* d_in, const int* in_sizes, int n_in,
                              void* d_out, int out_size)
{
    const float* f1   = (const float*)d_in[0];
    const float* f2   = (const float*)d_in[1];
    const int*   pre1 = (const int*)d_in[2];
    const int*   pre2 = (const int*)d_in[3];

    chan_mean_kernel<<<dim3(HW / (256 * 4), NB, 2), 256>>>(f1, f2);
    box_loss_kernel<<<2 * NK, 512>>>(pre1, pre2, (float*)d_out);
}

// round 4
// speedup vs baseline: 1.1482x; 1.0036x over previous
#include <cuda_runtime.h>

#define HALFW 6
#define MAXC  63
#define NK    21
#define NB    64
#define NC    256
#define NH    64
#define NW    64
#define HW    (NH * NW)
#define NBOX  (2 * NB * NK)        // 2688 boxes
#define BOX_BLOCKS (NBOX / 8)      // 336 blocks x 8 warps

// Scratch (allocation-free rule: __device__ globals)
__device__ float g_fm[2][NB][NH][NW];   // channel means, 2 MiB
__device__ float g_bm[2][NK][NB];       // per-box means
__device__ int   g_count = 0;           // completion counter (self-resetting)

// ---------------------------------------------------------------------------
// Kernel 1: fm[t][b][h][w] = (1/256) * sum_c f[b][c][h][w]
// PROVEN at ~77-80us / 85% DRAM — unchanged from round 1. Do not touch.
// grid = (HW/(256*4), B, 2), block = 256
// ---------------------------------------------------------------------------
__global__ void __launch_bounds__(256) chan_mean_kernel(
    const float* __restrict__ f1, const float* __restrict__ f2)
{
    const int t   = blockIdx.z;
    const int b   = blockIdx.y;
    const int hw4 = blockIdx.x * blockDim.x + threadIdx.x;   // 0..1023

    const float4* __restrict__ f4 =
        reinterpret_cast<const float4*>(t == 0 ? f1 : f2);
    const float4* __restrict__ p = f4 + (size_t)b * NC * (HW / 4) + hw4;

    float4 acc = make_float4(0.f, 0.f, 0.f, 0.f);
#pragma unroll 8
    for (int c = 0; c < NC; ++c) {
        float4 v = p[(size_t)c * (HW / 4)];
        acc.x += v.x; acc.y += v.y; acc.z += v.z; acc.w += v.w;
    }
    const float s = 1.0f / (float)NC;
    float4 o = make_float4(acc.x * s, acc.y * s, acc.z * s, acc.w * s);
    reinterpret_cast<float4*>(&g_fm[t][b][0][0])[hw4] = o;
}

// ---------------------------------------------------------------------------
// Kernel 2: warp-per-box box means (div-free, predicated 12x12 superset),
// then last-block-done computes batch-mean + MSE. One launch.
// grid = 336 blocks, block = 256 (8 warps -> 2688 warps = 2688 boxes)
// ---------------------------------------------------------------------------
__global__ void __launch_bounds__(256) box_loss_kernel(
    const int* __restrict__ pre1, const int* __restrict__ pre2,
    float* __restrict__ out)
{
    const int tid  = threadIdx.x;
    const int warp = tid >> 5;
    const int lane = tid & 31;
    const int wg   = blockIdx.x * 8 + warp;       // 0..2687

    const int t   = wg / (NB * NK);
    const int rem = wg - t * (NB * NK);
    const int b   = rem / NK;
    const int k   = rem - b * NK;

    const int* __restrict__ pre = (t == 0) ? pre1 : pre2;
    const int x = pre[(b * NK + k) * 2 + 0];
    const int y = pre[(b * NK + k) * 2 + 1];

    // x masks rows (H), y masks cols (W); exclusive upper bounds.
    const int left  = max(x - HALFW, 0);
    const int right = min(x + HALFW, MAXC);
    const int down  = max(y - HALFW, 0);
    const int up    = min(y + HALFW, MAXC);
    const int nh = right - left;                  // 6..12
    const int nw = up - down;                     // 6..12
    const float inv_cnt = 1.0f / (float)(nh * nw);

    const float* __restrict__ fm = &g_fm[t][b][0][0];
    float s = 0.f;
#pragma unroll
    for (int it = 0; it < 5; ++it) {
        const int idx = lane + 32 * it;           // 0..159
        const int r = idx / 12;                   // constant divisor -> mul/shift
        const int c = idx - r * 12;
        if ((idx < 144) && (r < nh) && (c < nw))
            s += fm[(left + r) * NW + (down + c)];
    }
#pragma unroll
    for (int off = 16; off > 0; off >>= 1)
        s += __shfl_down_sync(0xffffffffu, s, off);
    if (lane == 0)
        g_bm[t][k][b] = s * inv_cnt;              // each slot written once

    // ---- completion: last block finishes the reduction ----
    __shared__ int s_last;
    __syncthreads();                              // all warps' writes issued
    if (tid == 0) {
        __threadfence();                          // make g_bm visible
        s_last = (atomicAdd(&g_count, 1) == BOX_BLOCKS - 1) ? 1 : 0;
    }
    __syncthreads();
    if (!s_last) return;

    __threadfence();
    __shared__ float s_fea[2 * NK];
    for (int g = warp; g < 2 * NK; g += 8) {
        const int tt = g / NK;
        const int kk = g - tt * NK;
        // 64 batch values: 2 per lane; __ldcg to bypass L1 (cross-block data)
        float v = __ldcg(&g_bm[tt][kk][lane]) + __ldcg(&g_bm[tt][kk][lane + 32]);
#pragma unroll
        for (int off = 16; off > 0; off >>= 1)
            v += __shfl_down_sync(0xffffffffu, v, off);
        if (lane == 0)
            s_fea[g] = v * (1.0f / (float)NB);
    }
    __syncthreads();
    if (tid == 0) {
        float acc = 0.f;
#pragma unroll
        for (int kk = 0; kk < NK; ++kk) {
            const float d = s_fea[kk] - 0.999f * s_fea[NK + kk];
            acc += d * d;
        }
        out[0] = acc * (1.0f / (float)NK);
        g_count = 0;                              // reset for next replay
    }
}

extern "C" void kernel_launch(void* const* d_in, const int* in_sizes, int n_in,
                              void* d_out, int out_size)
{
    const float* f1   = (const float*)d_in[0];
    const float* f2   = (const float*)d_in[1];
    const int*   pre1 = (const int*)d_in[2];
    const int*   pre2 = (const int*)d_in[3];

    chan_mean_kernel<<<dim3(HW / (256 * 4), NB, 2), 256>>>(f1, f2);
    box_loss_kernel<<<BOX_BLOCKS, 256>>>(pre1, pre2, (float*)d_out);
}